// round 16
// baseline (speedup 1.0000x reference)
#include <cuda_runtime.h>
#include <cuda_fp16.h>
#include <cstdint>

#define BATCH 2
#define SEQL  2048
#define HISTL 2048
#define TTOT  4096
#define NHEAD 16
#define HD    128
#define DIM   2048
#define MROWS 4096

__device__ float  g_q[(size_t)MROWS * DIM];
__device__ __half g_ah[(size_t)MROWS * DIM];
__device__ __half g_xh[(size_t)MROWS * DIM];
__device__ __half g_wh[(size_t)4 * DIM * DIM];
__device__ __half g_kh[(size_t)BATCH * TTOT * DIM];
__device__ __half g_vt[(size_t)BATCH * NHEAD * HD * TTOT];

__device__ __forceinline__ unsigned h2u(__half2 h) { return *(unsigned*)&h; }

__device__ __forceinline__ void mma16(float* c, const unsigned* a, const unsigned* b) {
    asm volatile("mma.sync.aligned.m16n8k16.row.col.f32.f16.f16.f32 "
                 "{%0,%1,%2,%3}, {%4,%5,%6,%7}, {%8,%9}, {%0,%1,%2,%3};"
                 : "+f"(c[0]), "+f"(c[1]), "+f"(c[2]), "+f"(c[3])
                 : "r"(a[0]), "r"(a[1]), "r"(a[2]), "r"(a[3]),
                   "r"(b[0]), "r"(b[1]));
}

__device__ __forceinline__ void ldm4(unsigned* r, uint32_t addr) {
    asm volatile("ldmatrix.sync.aligned.m8n8.x4.shared.b16 {%0,%1,%2,%3}, [%4];"
                 : "=r"(r[0]), "=r"(r[1]), "=r"(r[2]), "=r"(r[3]) : "r"(addr));
}

__device__ __forceinline__ void cp16h(__half* s, const __half* g) {
    unsigned sa = (unsigned)__cvta_generic_to_shared(s);
    asm volatile("cp.async.cg.shared.global [%0], [%1], 16;" :: "r"(sa), "l"(g));
}
__device__ __forceinline__ void cp_commit() { asm volatile("cp.async.commit_group;"); }
__device__ __forceinline__ void cp_wait1()  { asm volatile("cp.async.wait_group 1;"); }

// ---------------------------------------------------------------------------
// f32 -> f16 conversion (single tensor)
// ---------------------------------------------------------------------------
__global__ void cvt_f16_kernel(const float* __restrict__ in, __half* __restrict__ out, int n4)
{
    int i = blockIdx.x * blockDim.x + threadIdx.x;
    if (i < n4) {
        float4 v = ((const float4*)in)[i];
        ((uint2*)out)[i] = make_uint2(h2u(__floats2half2_rn(v.x, v.y)),
                                      h2u(__floats2half2_rn(v.z, v.w)));
    }
}

// 4 weights -> contiguous half buffer in one launch
__global__ void cvt_w4_kernel(const float* __restrict__ w0, const float* __restrict__ w1,
                              const float* __restrict__ w2, const float* __restrict__ w3,
                              __half* __restrict__ out)
{
    const int nw4 = DIM * DIM / 4;
    const int i = blockIdx.x * blockDim.x + threadIdx.x;
    if (i >= 4 * nw4) return;
    const int which = i / nw4, e = i - which * nw4;
    const float* src = (which == 0) ? w0 : (which == 1) ? w1 : (which == 2) ? w2 : w3;
    float4 v = ((const float4*)src)[e];
    ((uint2*)out)[i] = make_uint2(h2u(__floats2half2_rn(v.x, v.y)),
                                  h2u(__floats2half2_rn(v.z, v.w)));
}

// ---------------------------------------------------------------------------
// History concat: prev_k/prev_v -> kall/vall[:, :HISTL] (f32) + K half copy
// ---------------------------------------------------------------------------
__global__ void concat_half_kernel(
    const float* __restrict__ pk, const float* __restrict__ pv,
    float* __restrict__ kall, float* __restrict__ vall, __half* __restrict__ kh)
{
    const int n4 = BATCH * HISTL * DIM / 4;
    const int i = blockIdx.x * blockDim.x + threadIdx.x;
    if (i >= 2 * n4) return;
    const bool isK = (i < n4);
    const int e = isK ? i : (i - n4);
    const int bb = e / (HISTL * DIM / 4);
    const int rem = e - bb * (HISTL * DIM / 4);
    const int dOff = bb * (TTOT * DIM / 4) + rem;
    float4 v = ((const float4*)(isK ? pk : pv))[e];
    ((float4*)(isK ? kall : vall))[dOff] = v;
    if (isK)
        ((uint2*)kh)[dOff] = make_uint2(h2u(__floats2half2_rn(v.x, v.y)),
                                        h2u(__floats2half2_rn(v.z, v.w)));
}

// ---------------------------------------------------------------------------
// V transpose: vall f32 [b, kv, h, d] -> vt half [b, h, d, kv]
// ---------------------------------------------------------------------------
__global__ void vtrans_kernel(const float* __restrict__ vall, __half* __restrict__ vt)
{
    __shared__ float smt[64][65];
    const int tid = threadIdx.x;
    const int kv0 = blockIdx.x * 64, d0 = blockIdx.y * 64;
    const int bh = blockIdx.z;
    const int b = bh >> 4, h = bh & 15;

    for (int idx = tid; idx < 64 * 16; idx += 256) {
        const int r = idx >> 4, c = (idx & 15) * 4;
        float4 v = *(const float4*)&vall[((size_t)b * TTOT + kv0 + r) * DIM + h * HD + d0 + c];
        smt[r][c] = v.x; smt[r][c + 1] = v.y; smt[r][c + 2] = v.z; smt[r][c + 3] = v.w;
    }
    __syncthreads();
    for (int idx = tid; idx < 64 * 8; idx += 256) {
        const int d = idx >> 3, ck = (idx & 7) * 8;
        unsigned u[4];
#pragma unroll
        for (int j = 0; j < 4; j++)
            u[j] = h2u(__floats2half2_rn(smt[ck + 2 * j][d], smt[ck + 2 * j + 1][d]));
        *(uint4*)&vt[((size_t)bh * HD + d0 + d) * TTOT + kv0 + ck] =
            make_uint4(u[0], u[1], u[2], u[3]);
    }
}

// ---------------------------------------------------------------------------
// QKV GEMM: CTA tile 64x128, 8 warps (warp 32x32), K32, 3-stage, 3 CTAs/SM.
// ---------------------------------------------------------------------------
#define RSH 40
#define A_ST3 (64 * RSH)
#define B_ST3 (128 * RSH)
#define STG3  (A_ST3 + B_ST3)
#define GST 3

__global__ __launch_bounds__(256, 3) void gemm_f16_qkv(
    const __half* __restrict__ A, const __half* __restrict__ Wbase,
    float* __restrict__ Cq, float* __restrict__ Ck, float* __restrict__ Cv,
    __half* __restrict__ CRk)
{
    extern __shared__ __align__(16) __half hsm[];

    const int z = blockIdx.z;
    const __half* Bw = Wbase + (size_t)z * DIM * DIM;
    float* C = (z == 0) ? Cq : (z == 1) ? Ck : Cv;
    __half* CR = (z == 1) ? CRk : nullptr;
    const int remap = (z != 0);

    const int tid = threadIdx.x, lane = tid & 31, warp = tid >> 5;
    const int g = lane >> 2, t = lane & 3;
    const int ln15 = lane & 15, hi8 = (lane >> 4) * 8;
    const int wm = (warp >> 2) * 32;
    const int wn = (warp & 3) * 32;
    const int bm = blockIdx.y * 64, bn = blockIdx.x * 128;

    const int arow = tid >> 2, aoff = (tid & 3) * 8;
    const __half* Ap = A + (size_t)(bm + arow) * DIM + aoff;
    const uint32_t S0 = (uint32_t)__cvta_generic_to_shared(hsm);

    float acc[2][4][4];
#pragma unroll
    for (int i = 0; i < 2; i++)
#pragma unroll
        for (int j = 0; j < 4; j++)
#pragma unroll
            for (int c = 0; c < 4; c++) acc[i][j][c] = 0.0f;

#define G3_ISSUE(kb, s) do { \
    cp16h(hsm + (s) * STG3 + arow * RSH + aoff, Ap + (kb)); \
    _Pragma("unroll") \
    for (int i = 0; i < 2; i++) { \
        const int ck = tid + 256 * i; \
        const int br = ck >> 2, bo = (ck & 3) * 8; \
        cp16h(hsm + (s) * STG3 + A_ST3 + br * RSH + bo, \
              Bw + (size_t)(bn + br) * DIM + (kb) + bo); \
    } \
} while (0)

    G3_ISSUE(0, 0);  cp_commit();
    G3_ISSUE(32, 1); cp_commit();

    const int nk = DIM / 32;
    for (int it = 0; it < nk; it++) {
        cp_wait1();
        __syncthreads();
        if (it + 2 < nk) { G3_ISSUE((it + 2) * 32, (it + 2) % GST); }
        cp_commit();

        const uint32_t Ash = S0 + (it % GST) * STG3 * 2;
        const uint32_t Bsh = Ash + A_ST3 * 2;
#pragma unroll
        for (int ks2 = 0; ks2 < 2; ks2++) {
            const int kcol = ks2 * 16 + hi8;
            unsigned af[2][4];
#pragma unroll
            for (int mt = 0; mt < 2; mt++)
                ldm4(af[mt], Ash + ((wm + mt * 16 + ln15) * RSH + kcol) * 2);
#pragma unroll
            for (int p = 0; p < 2; p++) {
                unsigned bq[4];
                ldm4(bq, Bsh + ((wn + p * 16 + ln15) * RSH + kcol) * 2);
#pragma unroll
                for (int sub = 0; sub < 2; sub++) {
                    unsigned bf[2] = { bq[sub], bq[sub + 2] };
#pragma unroll
                    for (int mt = 0; mt < 2; mt++)
                        mma16(acc[mt][p * 2 + sub], af[mt], bf);
                }
            }
        }
    }

#pragma unroll
    for (int mt = 0; mt < 2; mt++) {
        const int m0 = bm + wm + mt * 16 + g;
        const int m1 = m0 + 8;
        size_t ro0, ro1;
        if (!remap) {
            ro0 = (size_t)m0 * DIM; ro1 = (size_t)m1 * DIM;
        } else {
            ro0 = ((size_t)(m0 >> 11) * TTOT + HISTL + (m0 & 2047)) * DIM;
            ro1 = ((size_t)(m1 >> 11) * TTOT + HISTL + (m1 & 2047)) * DIM;
        }
#pragma unroll
        for (int nt = 0; nt < 4; nt++) {
            const int col = bn + wn + nt * 8 + 2 * t;
            *(float2*)&C[ro0 + col] = make_float2(acc[mt][nt][0], acc[mt][nt][1]);
            *(float2*)&C[ro1 + col] = make_float2(acc[mt][nt][2], acc[mt][nt][3]);
            if (CR != nullptr) {
                *(__half2*)&CR[ro0 + col] = __floats2half2_rn(acc[mt][nt][0], acc[mt][nt][1]);
                *(__half2*)&CR[ro1 + col] = __floats2half2_rn(acc[mt][nt][2], acc[mt][nt][3]);
            }
        }
    }
}

// ---------------------------------------------------------------------------
// Output-projection GEMM: same 64x128 / 3 CTAs-per-SM config, single output.
// ---------------------------------------------------------------------------
__global__ __launch_bounds__(256, 3) void gemm_f16_o(
    const __half* __restrict__ A, const __half* __restrict__ Bw,
    float* __restrict__ C)
{
    extern __shared__ __align__(16) __half hsm[];

    const int tid = threadIdx.x, lane = tid & 31, warp = tid >> 5;
    const int g = lane >> 2, t = lane & 3;
    const int ln15 = lane & 15, hi8 = (lane >> 4) * 8;
    const int wm = (warp >> 2) * 32;
    const int wn = (warp & 3) * 32;
    const int bm = blockIdx.y * 64, bn = blockIdx.x * 128;

    const int arow = tid >> 2, aoff = (tid & 3) * 8;
    const __half* Ap = A + (size_t)(bm + arow) * DIM + aoff;
    const uint32_t S0 = (uint32_t)__cvta_generic_to_shared(hsm);

    float acc[2][4][4];
#pragma unroll
    for (int i = 0; i < 2; i++)
#pragma unroll
        for (int j = 0; j < 4; j++)
#pragma unroll
            for (int c = 0; c < 4; c++) acc[i][j][c] = 0.0f;

    G3_ISSUE(0, 0);  cp_commit();
    G3_ISSUE(32, 1); cp_commit();

    const int nk = DIM / 32;
    for (int it = 0; it < nk; it++) {
        cp_wait1();
        __syncthreads();
        if (it + 2 < nk) { G3_ISSUE((it + 2) * 32, (it + 2) % GST); }
        cp_commit();

        const uint32_t Ash = S0 + (it % GST) * STG3 * 2;
        const uint32_t Bsh = Ash + A_ST3 * 2;
#pragma unroll
        for (int ks2 = 0; ks2 < 2; ks2++) {
            const int kcol = ks2 * 16 + hi8;
            unsigned af[2][4];
#pragma unroll
            for (int mt = 0; mt < 2; mt++)
                ldm4(af[mt], Ash + ((wm + mt * 16 + ln15) * RSH + kcol) * 2);
#pragma unroll
            for (int p = 0; p < 2; p++) {
                unsigned bq[4];
                ldm4(bq, Bsh + ((wn + p * 16 + ln15) * RSH + kcol) * 2);
#pragma unroll
                for (int sub = 0; sub < 2; sub++) {
                    unsigned bf[2] = { bq[sub], bq[sub + 2] };
#pragma unroll
                    for (int mt = 0; mt < 2; mt++)
                        mma16(acc[mt][p * 2 + sub], af[mt], bf);
                }
            }
        }
    }

#pragma unroll
    for (int mt = 0; mt < 2; mt++) {
        const int m0 = bm + wm + mt * 16 + g;
        const int m1 = m0 + 8;
        const size_t ro0 = (size_t)m0 * DIM, ro1 = (size_t)m1 * DIM;
#pragma unroll
        for (int nt = 0; nt < 4; nt++) {
            const int col = bn + wn + nt * 8 + 2 * t;
            *(float2*)&C[ro0 + col] = make_float2(acc[mt][nt][0], acc[mt][nt][1]);
            *(float2*)&C[ro1 + col] = make_float2(acc[mt][nt][2], acc[mt][nt][3]);
        }
    }
}

// ---------------------------------------------------------------------------
// FP16 flash attention v7: Q in SMEM, P in regs, K/V double-buffered,
// 2 CTAs/SM. BQ=128, warp owns 16 rows, qt reversed.
// ---------------------------------------------------------------------------
#define BQA 128
#define QSH 136
#define KSH 136
#define VTH 72
#define AOFF_Q  0
#define AOFF_K0 (128 * QSH)
#define AOFF_K1 (AOFF_K0 + 64 * KSH)
#define AOFF_V0 (AOFF_K1 + 64 * KSH)
#define AOFF_V1 (AOFF_V0 + 128 * VTH)
#define ATT_SMEM ((AOFF_V1 + 128 * VTH) * 2)   // 106496 bytes

__global__ __launch_bounds__(256, 2) void attn_f16(
    const float* __restrict__ q, const __half* __restrict__ kh,
    const __half* __restrict__ vt, __half* __restrict__ outp)
{
    extern __shared__ __align__(16) __half smh[];

    const int tid = threadIdx.x, lane = tid & 31, warp = tid >> 5;
    const int g = lane >> 2, t = lane & 3;
    const int ln15 = lane & 15, hi8 = (lane >> 4) * 8;
    const int qt = gridDim.x - 1 - blockIdx.x;
    const int h = blockIdx.y, b = blockIdx.z;
    const int wq = warp * 16;

    const size_t kbase = (size_t)b * TTOT * DIM + h * HD;
    const size_t vbase = ((size_t)b * NHEAD + h) * HD * TTOT;

    const uint32_t S0 = (uint32_t)__cvta_generic_to_shared(smh);
    const uint32_t Qsh = S0 + AOFF_Q * 2;

#define KV_ISSUE(kt, st) do { \
    __half* Kd = smh + ((st) ? AOFF_K1 : AOFF_K0); \
    __half* Vd = smh + ((st) ? AOFF_V1 : AOFF_V0); \
    const size_t kg = kbase + (size_t)((kt) * 64) * DIM; \
    const size_t vg = vbase + (kt) * 64; \
    _Pragma("unroll") \
    for (int i = 0; i < 4; i++) { \
        const int ck = tid + 256 * i; \
        const int kr = ck >> 4, ko = (ck & 15) * 8; \
        cp16h(&Kd[kr * KSH + ko], kh + kg + (size_t)kr * DIM + ko); \
        const int vr = ck >> 3, vo = (ck & 7) * 8; \
        cp16h(&Vd[vr * VTH + vo], vt + vg + (size_t)vr * TTOT + vo); \
    } \
} while (0)

    // Q tile -> smem (f32 -> half, bit-exact same rounding as register path)
    {
        const float* qsrc = q + (size_t)(b * SEQL + qt * BQA) * DIM + h * HD;
        for (int idx = tid; idx < 128 * 16; idx += 256) {
            const int r = idx >> 4, c = (idx & 15) * 8;
            float4 v0 = *(const float4*)&qsrc[(size_t)r * DIM + c];
            float4 v1 = *(const float4*)&qsrc[(size_t)r * DIM + c + 4];
            *(uint4*)&smh[AOFF_Q + r * QSH + c] =
                make_uint4(h2u(__floats2half2_rn(v0.x, v0.y)),
                           h2u(__floats2half2_rn(v0.z, v0.w)),
                           h2u(__floats2half2_rn(v1.x, v1.y)),
                           h2u(__floats2half2_rn(v1.z, v1.w)));
        }
    }

    float O[16][4];
#pragma unroll
    for (int i = 0; i < 16; i++)
#pragma unroll
        for (int c = 0; c < 4; c++) O[i][c] = 0.0f;
    float m0 = -1e30f, m1 = -1e30f, l0 = 0.0f, l1 = 0.0f;

    const int ntiles = HISTL / 64 + 2 * qt + 2;
    const float scale = 0.08838834764831845f;

    KV_ISSUE(0, 0); cp_commit();

    for (int kt = 0; kt < ntiles; kt++) {
        __syncthreads();           // prev compute done (and Q visible at kt=0)
        if (kt + 1 < ntiles) { KV_ISSUE(kt + 1, (kt + 1) & 1); }
        cp_commit();
        cp_wait1();                // K/V (kt) resident
        __syncthreads();

        const uint32_t Ksh = S0 + (((kt & 1) ? AOFF_K1 : AOFF_K0)) * 2;
        const uint32_t Vsh = S0 + (((kt & 1) ? AOFF_V1 : AOFF_V0)) * 2;

        // ---- S = Q K^T : 16q x 64kv per warp ----
        float s[8][4];
#pragma unroll
        for (int nt = 0; nt < 8; nt++)
#pragma unroll
            for (int c = 0; c < 4; c++) s[nt][c] = 0.0f;

#pragma unroll
        for (int kc = 0; kc < 8; kc++) {
            const int kcol = kc * 16 + hi8;
            unsigned aq[4];
            ldm4(aq, Qsh + ((wq + ln15) * QSH + kcol) * 2);
#pragma unroll
            for (int p = 0; p < 4; p++) {
                unsigned kq[4];
                ldm4(kq, Ksh + ((p * 16 + ln15) * KSH + kcol) * 2);
#pragma unroll
                for (int sub = 0; sub < 2; sub++) {
                    unsigned bf[2] = { kq[sub], kq[sub + 2] };
                    mma16(s[p * 2 + sub], aq, bf);
                }
            }
        }

        const bool needmask = (kt >= ntiles - 2);
        const int diagoff = HISTL + qt * BQA - kt * 64;
#pragma unroll
        for (int nt = 0; nt < 8; nt++) {
#pragma unroll
            for (int c = 0; c < 4; c++) {
                float v = s[nt][c] * scale;
                if (needmask) {
                    const int rrow = wq + g + ((c >= 2) ? 8 : 0);
                    const int col = nt * 8 + 2 * t + (c & 1);
                    if (col > rrow + diagoff) v = -1e30f;
                }
                s[nt][c] = v;
            }
        }

        float rm0 = -1e30f, rm1 = -1e30f;
#pragma unroll
        for (int nt = 0; nt < 8; nt++) {
            rm0 = fmaxf(rm0, fmaxf(s[nt][0], s[nt][1]));
            rm1 = fmaxf(rm1, fmaxf(s[nt][2], s[nt][3]));
        }
#pragma unroll
        for (int off = 1; off <= 2; off <<= 1) {
            rm0 = fmaxf(rm0, __shfl_xor_sync(0xffffffffu, rm0, off));
            rm1 = fmaxf(rm1, __shfl_xor_sync(0xffffffffu, rm1, off));
        }
        const float mn0 = fmaxf(m0, rm0), mn1 = fmaxf(m1, rm1);
        const float al0 = __expf(m0 - mn0), al1 = __expf(m1 - mn1);

        float rs0 = 0.0f, rs1 = 0.0f;
        unsigned pa[8], pb[8];
#pragma unroll
        for (int nt = 0; nt < 8; nt++) {
            float p0 = __expf(s[nt][0] - mn0);
            float p1 = __expf(s[nt][1] - mn0);
            float p2 = __expf(s[nt][2] - mn1);
            float p3 = __expf(s[nt][3] - mn1);
            rs0 += p0 + p1; rs1 += p2 + p3;
            pa[nt] = h2u(__floats2half2_rn(p0, p1));
            pb[nt] = h2u(__floats2half2_rn(p2, p3));
        }
#pragma unroll
        for (int off = 1; off <= 2; off <<= 1) {
            rs0 += __shfl_xor_sync(0xffffffffu, rs0, off);
            rs1 += __shfl_xor_sync(0xffffffffu, rs1, off);
        }
        l0 = l0 * al0 + rs0;
        l1 = l1 * al1 + rs1;
        m0 = mn0; m1 = mn1;

#pragma unroll
        for (int nt = 0; nt < 16; nt++) {
            O[nt][0] *= al0; O[nt][1] *= al0;
            O[nt][2] *= al1; O[nt][3] *= al1;
        }

        // ---- O += P V : 16q x 128d per warp, P from registers ----
#pragma unroll
        for (int kc = 0; kc < 4; kc++) {
            const int kcol = kc * 16 + hi8;
            unsigned af[4] = { pa[2 * kc], pb[2 * kc], pa[2 * kc + 1], pb[2 * kc + 1] };
#pragma unroll
            for (int p = 0; p < 8; p++) {
                unsigned vq[4];
                ldm4(vq, Vsh + ((p * 16 + ln15) * VTH + kcol) * 2);
#pragma unroll
                for (int sub = 0; sub < 2; sub++) {
                    unsigned bf[2] = { vq[sub], vq[sub + 2] };
                    mma16(O[p * 2 + sub], af, bf);
                }
            }
        }
    }

    const float inv0 = 1.0f / l0, inv1 = 1.0f / l1;
#pragma unroll
    for (int nt = 0; nt < 16; nt++) {
        const int col = h * HD + nt * 8 + 2 * t;
        const size_t r0 = (size_t)(b * SEQL + qt * BQA + wq + g)     * DIM + col;
        const size_t r1 = (size_t)(b * SEQL + qt * BQA + wq + g + 8) * DIM + col;
        *(__half2*)&outp[r0] = __floats2half2_rn(O[nt][0] * inv0, O[nt][1] * inv0);
        *(__half2*)&outp[r1] = __floats2half2_rn(O[nt][2] * inv1, O[nt][3] * inv1);
    }
}

// ---------------------------------------------------------------------------
extern "C" void kernel_launch(void* const* d_in, const int* in_sizes, int n_in,
                              void* d_out, int out_size)
{
    const float* x  = (const float*)d_in[0];
    const float* pk = (const float*)d_in[1];
    const float* pv = (const float*)d_in[2];
    const float* wq = (const float*)d_in[4];
    const float* wk = (const float*)d_in[5];
    const float* wv = (const float*)d_in[6];
    const float* wo = (const float*)d_in[7];

    float* out  = (float*)d_out;
    float* kall = out  + (size_t)BATCH * SEQL * DIM;
    float* vall = kall + (size_t)BATCH * TTOT * DIM;

    float *qbuf; __half *ah, *xh, *wh, *kh, *vt;
    cudaGetSymbolAddress((void**)&qbuf, g_q);
    cudaGetSymbolAddress((void**)&ah,   g_ah);
    cudaGetSymbolAddress((void**)&xh,   g_xh);
    cudaGetSymbolAddress((void**)&wh,   g_wh);
    cudaGetSymbolAddress((void**)&kh,   g_kh);
    cudaGetSymbolAddress((void**)&vt,   g_vt);

    {
        const int tot = 2 * BATCH * HISTL * DIM / 4;
        concat_half_kernel<<<(tot + 255) / 256, 256>>>(pk, pv, kall, vall, kh);
    }
    {
        const int nx4 = MROWS * DIM / 4;
        cvt_f16_kernel<<<(nx4 + 255) / 256, 256>>>(x, xh, nx4);
        const int nwtot = 4 * DIM * DIM / 4;
        cvt_w4_kernel<<<(nwtot + 255) / 256, 256>>>(wq, wk, wv, wo, wh);
    }

    const int gsm3 = (int)(GST * STG3 * sizeof(__half));  // 46080
    cudaFuncSetAttribute(gemm_f16_qkv, cudaFuncAttributeMaxDynamicSharedMemorySize, gsm3);
    cudaFuncSetAttribute(gemm_f16_o,   cudaFuncAttributeMaxDynamicSharedMemorySize, gsm3);

    gemm_f16_qkv<<<dim3(DIM / 128, MROWS / 64, 3), 256, gsm3>>>(
        xh, wh, qbuf, kall, vall, kh);

    vtrans_kernel<<<dim3(TTOT / 64, HD / 64, BATCH * NHEAD), 256>>>(vall, vt);

    cudaFuncSetAttribute(attn_f16, cudaFuncAttributeMaxDynamicSharedMemorySize, ATT_SMEM);
    attn_f16<<<dim3(SEQL / BQA, NHEAD, BATCH), 256, ATT_SMEM>>>(qbuf, kh, vt, ah);

    gemm_f16_o<<<dim3(DIM / 128, MROWS / 64), 256, gsm3>>>(
        ah, wh + 3 * (size_t)DIM * DIM, out);
}

// round 17
// speedup vs baseline: 1.0475x; 1.0475x over previous
#include <cuda_runtime.h>
#include <cuda_fp16.h>
#include <cstdint>

#define BATCH 2
#define SEQL  2048
#define HISTL 2048
#define TTOT  4096
#define NHEAD 16
#define HD    128
#define DIM   2048
#define MROWS 4096

__device__ float  g_q[(size_t)MROWS * DIM];
__device__ __half g_ah[(size_t)MROWS * DIM];
__device__ __half g_xh[(size_t)MROWS * DIM];
__device__ __half g_wh[(size_t)4 * DIM * DIM];
__device__ __half g_kh[(size_t)BATCH * TTOT * DIM];
__device__ __half g_vt[(size_t)BATCH * NHEAD * HD * TTOT];

__device__ __forceinline__ unsigned h2u(__half2 h) { return *(unsigned*)&h; }

__device__ __forceinline__ void mma16(float* c, const unsigned* a, const unsigned* b) {
    asm volatile("mma.sync.aligned.m16n8k16.row.col.f32.f16.f16.f32 "
                 "{%0,%1,%2,%3}, {%4,%5,%6,%7}, {%8,%9}, {%0,%1,%2,%3};"
                 : "+f"(c[0]), "+f"(c[1]), "+f"(c[2]), "+f"(c[3])
                 : "r"(a[0]), "r"(a[1]), "r"(a[2]), "r"(a[3]),
                   "r"(b[0]), "r"(b[1]));
}

__device__ __forceinline__ void ldm4(unsigned* r, uint32_t addr) {
    asm volatile("ldmatrix.sync.aligned.m8n8.x4.shared.b16 {%0,%1,%2,%3}, [%4];"
                 : "=r"(r[0]), "=r"(r[1]), "=r"(r[2]), "=r"(r[3]) : "r"(addr));
}

__device__ __forceinline__ void cp16h(__half* s, const __half* g) {
    unsigned sa = (unsigned)__cvta_generic_to_shared(s);
    asm volatile("cp.async.cg.shared.global [%0], [%1], 16;" :: "r"(sa), "l"(g));
}
__device__ __forceinline__ void cp_commit() { asm volatile("cp.async.commit_group;"); }
__device__ __forceinline__ void cp_wait1()  { asm volatile("cp.async.wait_group 1;"); }

// ---------------------------------------------------------------------------
// f32 -> f16 conversion (single tensor)
// ---------------------------------------------------------------------------
__global__ void cvt_f16_kernel(const float* __restrict__ in, __half* __restrict__ out, int n4)
{
    int i = blockIdx.x * blockDim.x + threadIdx.x;
    if (i < n4) {
        float4 v = ((const float4*)in)[i];
        ((uint2*)out)[i] = make_uint2(h2u(__floats2half2_rn(v.x, v.y)),
                                      h2u(__floats2half2_rn(v.z, v.w)));
    }
}

// 4 weights -> contiguous half buffer in one launch
__global__ void cvt_w4_kernel(const float* __restrict__ w0, const float* __restrict__ w1,
                              const float* __restrict__ w2, const float* __restrict__ w3,
                              __half* __restrict__ out)
{
    const int nw4 = DIM * DIM / 4;
    const int i = blockIdx.x * blockDim.x + threadIdx.x;
    if (i >= 4 * nw4) return;
    const int which = i / nw4, e = i - which * nw4;
    const float* src = (which == 0) ? w0 : (which == 1) ? w1 : (which == 2) ? w2 : w3;
    float4 v = ((const float4*)src)[e];
    ((uint2*)out)[i] = make_uint2(h2u(__floats2half2_rn(v.x, v.y)),
                                  h2u(__floats2half2_rn(v.z, v.w)));
}

// ---------------------------------------------------------------------------
// History concat: prev_k/prev_v -> kall/vall[:, :HISTL] (f32) + K half copy
// ---------------------------------------------------------------------------
__global__ void concat_half_kernel(
    const float* __restrict__ pk, const float* __restrict__ pv,
    float* __restrict__ kall, float* __restrict__ vall, __half* __restrict__ kh)
{
    const int n4 = BATCH * HISTL * DIM / 4;
    const int i = blockIdx.x * blockDim.x + threadIdx.x;
    if (i >= 2 * n4) return;
    const bool isK = (i < n4);
    const int e = isK ? i : (i - n4);
    const int bb = e / (HISTL * DIM / 4);
    const int rem = e - bb * (HISTL * DIM / 4);
    const int dOff = bb * (TTOT * DIM / 4) + rem;
    float4 v = ((const float4*)(isK ? pk : pv))[e];
    ((float4*)(isK ? kall : vall))[dOff] = v;
    if (isK)
        ((uint2*)kh)[dOff] = make_uint2(h2u(__floats2half2_rn(v.x, v.y)),
                                        h2u(__floats2half2_rn(v.z, v.w)));
}

// ---------------------------------------------------------------------------
// V transpose: vall f32 [b, kv, h, d] -> vt half [b, h, d, kv]
// ---------------------------------------------------------------------------
__global__ void vtrans_kernel(const float* __restrict__ vall, __half* __restrict__ vt)
{
    __shared__ float smt[64][65];
    const int tid = threadIdx.x;
    const int kv0 = blockIdx.x * 64, d0 = blockIdx.y * 64;
    const int bh = blockIdx.z;
    const int b = bh >> 4, h = bh & 15;

    for (int idx = tid; idx < 64 * 16; idx += 256) {
        const int r = idx >> 4, c = (idx & 15) * 4;
        float4 v = *(const float4*)&vall[((size_t)b * TTOT + kv0 + r) * DIM + h * HD + d0 + c];
        smt[r][c] = v.x; smt[r][c + 1] = v.y; smt[r][c + 2] = v.z; smt[r][c + 3] = v.w;
    }
    __syncthreads();
    for (int idx = tid; idx < 64 * 8; idx += 256) {
        const int d = idx >> 3, ck = (idx & 7) * 8;
        unsigned u[4];
#pragma unroll
        for (int j = 0; j < 4; j++)
            u[j] = h2u(__floats2half2_rn(smt[ck + 2 * j][d], smt[ck + 2 * j + 1][d]));
        *(uint4*)&vt[((size_t)bh * HD + d0 + d) * TTOT + kv0 + ck] =
            make_uint4(u[0], u[1], u[2], u[3]);
    }
}

// ---------------------------------------------------------------------------
// QKV GEMM: CTA tile 64x128, 8 warps (warp 32x32), K32, 3-stage, 3 CTAs/SM.
// ---------------------------------------------------------------------------
#define RSH 40
#define A_ST3 (64 * RSH)
#define B_ST3 (128 * RSH)
#define STG3  (A_ST3 + B_ST3)
#define GST 3

__global__ __launch_bounds__(256, 3) void gemm_f16_qkv(
    const __half* __restrict__ A, const __half* __restrict__ Wbase,
    float* __restrict__ Cq, float* __restrict__ Ck, float* __restrict__ Cv,
    __half* __restrict__ CRk)
{
    extern __shared__ __align__(16) __half hsm[];

    const int z = blockIdx.z;
    const __half* Bw = Wbase + (size_t)z * DIM * DIM;
    float* C = (z == 0) ? Cq : (z == 1) ? Ck : Cv;
    __half* CR = (z == 1) ? CRk : nullptr;
    const int remap = (z != 0);

    const int tid = threadIdx.x, lane = tid & 31, warp = tid >> 5;
    const int g = lane >> 2, t = lane & 3;
    const int ln15 = lane & 15, hi8 = (lane >> 4) * 8;
    const int wm = (warp >> 2) * 32;
    const int wn = (warp & 3) * 32;
    const int bm = blockIdx.y * 64, bn = blockIdx.x * 128;

    const int arow = tid >> 2, aoff = (tid & 3) * 8;
    const __half* Ap = A + (size_t)(bm + arow) * DIM + aoff;
    const uint32_t S0 = (uint32_t)__cvta_generic_to_shared(hsm);

    float acc[2][4][4];
#pragma unroll
    for (int i = 0; i < 2; i++)
#pragma unroll
        for (int j = 0; j < 4; j++)
#pragma unroll
            for (int c = 0; c < 4; c++) acc[i][j][c] = 0.0f;

#define G3_ISSUE(kb, s) do { \
    cp16h(hsm + (s) * STG3 + arow * RSH + aoff, Ap + (kb)); \
    _Pragma("unroll") \
    for (int i = 0; i < 2; i++) { \
        const int ck = tid + 256 * i; \
        const int br = ck >> 2, bo = (ck & 3) * 8; \
        cp16h(hsm + (s) * STG3 + A_ST3 + br * RSH + bo, \
              Bw + (size_t)(bn + br) * DIM + (kb) + bo); \
    } \
} while (0)

    G3_ISSUE(0, 0);  cp_commit();
    G3_ISSUE(32, 1); cp_commit();

    const int nk = DIM / 32;
    for (int it = 0; it < nk; it++) {
        cp_wait1();
        __syncthreads();
        if (it + 2 < nk) { G3_ISSUE((it + 2) * 32, (it + 2) % GST); }
        cp_commit();

        const uint32_t Ash = S0 + (it % GST) * STG3 * 2;
        const uint32_t Bsh = Ash + A_ST3 * 2;
#pragma unroll
        for (int ks2 = 0; ks2 < 2; ks2++) {
            const int kcol = ks2 * 16 + hi8;
            unsigned af[2][4];
#pragma unroll
            for (int mt = 0; mt < 2; mt++)
                ldm4(af[mt], Ash + ((wm + mt * 16 + ln15) * RSH + kcol) * 2);
#pragma unroll
            for (int p = 0; p < 2; p++) {
                unsigned bq[4];
                ldm4(bq, Bsh + ((wn + p * 16 + ln15) * RSH + kcol) * 2);
#pragma unroll
                for (int sub = 0; sub < 2; sub++) {
                    unsigned bf[2] = { bq[sub], bq[sub + 2] };
#pragma unroll
                    for (int mt = 0; mt < 2; mt++)
                        mma16(acc[mt][p * 2 + sub], af[mt], bf);
                }
            }
        }
    }

#pragma unroll
    for (int mt = 0; mt < 2; mt++) {
        const int m0 = bm + wm + mt * 16 + g;
        const int m1 = m0 + 8;
        size_t ro0, ro1;
        if (!remap) {
            ro0 = (size_t)m0 * DIM; ro1 = (size_t)m1 * DIM;
        } else {
            ro0 = ((size_t)(m0 >> 11) * TTOT + HISTL + (m0 & 2047)) * DIM;
            ro1 = ((size_t)(m1 >> 11) * TTOT + HISTL + (m1 & 2047)) * DIM;
        }
#pragma unroll
        for (int nt = 0; nt < 4; nt++) {
            const int col = bn + wn + nt * 8 + 2 * t;
            *(float2*)&C[ro0 + col] = make_float2(acc[mt][nt][0], acc[mt][nt][1]);
            *(float2*)&C[ro1 + col] = make_float2(acc[mt][nt][2], acc[mt][nt][3]);
            if (CR != nullptr) {
                *(__half2*)&CR[ro0 + col] = __floats2half2_rn(acc[mt][nt][0], acc[mt][nt][1]);
                *(__half2*)&CR[ro1 + col] = __floats2half2_rn(acc[mt][nt][2], acc[mt][nt][3]);
            }
        }
    }
}

// ---------------------------------------------------------------------------
// Output-projection GEMM: same 64x128 / 3 CTAs-per-SM config, single output.
// ---------------------------------------------------------------------------
__global__ __launch_bounds__(256, 3) void gemm_f16_o(
    const __half* __restrict__ A, const __half* __restrict__ Bw,
    float* __restrict__ C)
{
    extern __shared__ __align__(16) __half hsm[];

    const int tid = threadIdx.x, lane = tid & 31, warp = tid >> 5;
    const int g = lane >> 2, t = lane & 3;
    const int ln15 = lane & 15, hi8 = (lane >> 4) * 8;
    const int wm = (warp >> 2) * 32;
    const int wn = (warp & 3) * 32;
    const int bm = blockIdx.y * 64, bn = blockIdx.x * 128;

    const int arow = tid >> 2, aoff = (tid & 3) * 8;
    const __half* Ap = A + (size_t)(bm + arow) * DIM + aoff;
    const uint32_t S0 = (uint32_t)__cvta_generic_to_shared(hsm);

    float acc[2][4][4];
#pragma unroll
    for (int i = 0; i < 2; i++)
#pragma unroll
        for (int j = 0; j < 4; j++)
#pragma unroll
            for (int c = 0; c < 4; c++) acc[i][j][c] = 0.0f;

    G3_ISSUE(0, 0);  cp_commit();
    G3_ISSUE(32, 1); cp_commit();

    const int nk = DIM / 32;
    for (int it = 0; it < nk; it++) {
        cp_wait1();
        __syncthreads();
        if (it + 2 < nk) { G3_ISSUE((it + 2) * 32, (it + 2) % GST); }
        cp_commit();

        const uint32_t Ash = S0 + (it % GST) * STG3 * 2;
        const uint32_t Bsh = Ash + A_ST3 * 2;
#pragma unroll
        for (int ks2 = 0; ks2 < 2; ks2++) {
            const int kcol = ks2 * 16 + hi8;
            unsigned af[2][4];
#pragma unroll
            for (int mt = 0; mt < 2; mt++)
                ldm4(af[mt], Ash + ((wm + mt * 16 + ln15) * RSH + kcol) * 2);
#pragma unroll
            for (int p = 0; p < 2; p++) {
                unsigned bq[4];
                ldm4(bq, Bsh + ((wn + p * 16 + ln15) * RSH + kcol) * 2);
#pragma unroll
                for (int sub = 0; sub < 2; sub++) {
                    unsigned bf[2] = { bq[sub], bq[sub + 2] };
#pragma unroll
                    for (int mt = 0; mt < 2; mt++)
                        mma16(acc[mt][p * 2 + sub], af[mt], bf);
                }
            }
        }
    }

#pragma unroll
    for (int mt = 0; mt < 2; mt++) {
        const int m0 = bm + wm + mt * 16 + g;
        const int m1 = m0 + 8;
        const size_t ro0 = (size_t)m0 * DIM, ro1 = (size_t)m1 * DIM;
#pragma unroll
        for (int nt = 0; nt < 4; nt++) {
            const int col = bn + wn + nt * 8 + 2 * t;
            *(float2*)&C[ro0 + col] = make_float2(acc[mt][nt][0], acc[mt][nt][1]);
            *(float2*)&C[ro1 + col] = make_float2(acc[mt][nt][2], acc[mt][nt][3]);
        }
    }
}

// ---------------------------------------------------------------------------
// FP16 flash attention v8: 128-kv tiles (half the softmax/barrier passes).
// Q in regs, P in regs, K/V double-buffered, BQ=128, qt reversed.
// ---------------------------------------------------------------------------
#define BQA 128
#define KSH 136   // K row stride (128 data + 8)
#define VTH 136   // Vt row stride (128 kv data + 8)
#define BOFF_K0 0
#define BOFF_K1 (128 * KSH)
#define BOFF_V0 (2 * 128 * KSH)
#define BOFF_V1 (2 * 128 * KSH + 128 * VTH)
#define ATT_SMEM ((2 * 128 * KSH + 2 * 128 * VTH) * 2)   // 139264 bytes

__global__ __launch_bounds__(256) void attn_f16(
    const float* __restrict__ q, const __half* __restrict__ kh,
    const __half* __restrict__ vt, __half* __restrict__ outp)
{
    extern __shared__ __align__(16) __half smh[];

    const int tid = threadIdx.x, lane = tid & 31, warp = tid >> 5;
    const int g = lane >> 2, t = lane & 3;
    const int ln15 = lane & 15, hi8 = (lane >> 4) * 8;
    const int qt = gridDim.x - 1 - blockIdx.x;
    const int h = blockIdx.y, b = blockIdx.z;
    const int wq = warp * 16;

    const size_t kbase = (size_t)b * TTOT * DIM + h * HD;
    const size_t vbase = ((size_t)b * NHEAD + h) * HD * TTOT;
    const uint32_t S0 = (uint32_t)__cvta_generic_to_shared(smh);

#define KV_ISSUE(kt, st) do { \
    __half* Kd = smh + ((st) ? BOFF_K1 : BOFF_K0); \
    __half* Vd = smh + ((st) ? BOFF_V1 : BOFF_V0); \
    const size_t kg = kbase + (size_t)((kt) * 128) * DIM; \
    const size_t vg = vbase + (kt) * 128; \
    _Pragma("unroll") \
    for (int i = 0; i < 8; i++) { \
        const int ck = tid + 256 * i; \
        const int kr = ck >> 4, ko = (ck & 15) * 8; \
        cp16h(&Kd[kr * KSH + ko], kh + kg + (size_t)kr * DIM + ko); \
        cp16h(&Vd[kr * VTH + ko], vt + vg + (size_t)kr * TTOT + ko); \
    } \
} while (0)

    // Q -> half2 registers
    unsigned qa[8][4];
    {
        const size_t qbase = (size_t)(b * SEQL + qt * BQA + wq) * DIM + h * HD;
        const float* q0 = q + qbase + (size_t)g * DIM;
        const float* q1 = q + qbase + (size_t)(g + 8) * DIM;
#pragma unroll
        for (int kc = 0; kc < 8; kc++) {
            const int k0 = kc * 16 + 2 * t;
            qa[kc][0] = h2u(__floats2half2_rn(q0[k0],     q0[k0 + 1]));
            qa[kc][1] = h2u(__floats2half2_rn(q1[k0],     q1[k0 + 1]));
            qa[kc][2] = h2u(__floats2half2_rn(q0[k0 + 8], q0[k0 + 9]));
            qa[kc][3] = h2u(__floats2half2_rn(q1[k0 + 8], q1[k0 + 9]));
        }
    }

    float O[16][4];
#pragma unroll
    for (int i = 0; i < 16; i++)
#pragma unroll
        for (int c = 0; c < 4; c++) O[i][c] = 0.0f;
    float m0 = -1e30f, m1 = -1e30f, l0 = 0.0f, l1 = 0.0f;

    const int ntiles = HISTL / 128 + qt + 1;   // 17 + qt
    const float scale = 0.08838834764831845f;

    KV_ISSUE(0, 0); cp_commit();

    for (int kt = 0; kt < ntiles; kt++) {
        __syncthreads();
        if (kt + 1 < ntiles) { KV_ISSUE(kt + 1, (kt + 1) & 1); }
        cp_commit();
        cp_wait1();
        __syncthreads();

        const uint32_t Ksh = S0 + (((kt & 1) ? BOFF_K1 : BOFF_K0)) * 2;
        const uint32_t Vsh = S0 + (((kt & 1) ? BOFF_V1 : BOFF_V0)) * 2;

        // ---- S = Q K^T : 16q x 128kv per warp ----
        float s[16][4];
#pragma unroll
        for (int nt = 0; nt < 16; nt++)
#pragma unroll
            for (int c = 0; c < 4; c++) s[nt][c] = 0.0f;

#pragma unroll
        for (int kc = 0; kc < 8; kc++) {
            const int kcol = kc * 16 + hi8;
#pragma unroll
            for (int p = 0; p < 8; p++) {
                unsigned kq[4];
                ldm4(kq, Ksh + ((p * 16 + ln15) * KSH + kcol) * 2);
#pragma unroll
                for (int sub = 0; sub < 2; sub++) {
                    unsigned bf[2] = { kq[sub], kq[sub + 2] };
                    mma16(s[p * 2 + sub], qa[kc], bf);
                }
            }
        }

        // scale + causal mask (only the last 128-kv tile touches the diagonal)
        const bool needmask = (kt == ntiles - 1);
#pragma unroll
        for (int nt = 0; nt < 16; nt++) {
#pragma unroll
            for (int c = 0; c < 4; c++) {
                float v = s[nt][c] * scale;
                if (needmask) {
                    const int rrow = wq + g + ((c >= 2) ? 8 : 0);
                    const int col = nt * 8 + 2 * t + (c & 1);
                    if (col > rrow) v = -1e30f;   // diagoff == 0 on last tile
                }
                s[nt][c] = v;
            }
        }

        // online softmax: single pass per 128 kv
        float rm0 = -1e30f, rm1 = -1e30f;
#pragma unroll
        for (int nt = 0; nt < 16; nt++) {
            rm0 = fmaxf(rm0, fmaxf(s[nt][0], s[nt][1]));
            rm1 = fmaxf(rm1, fmaxf(s[nt][2], s[nt][3]));
        }
#pragma unroll
        for (int off = 1; off <= 2; off <<= 1) {
            rm0 = fmaxf(rm0, __shfl_xor_sync(0xffffffffu, rm0, off));
            rm1 = fmaxf(rm1, __shfl_xor_sync(0xffffffffu, rm1, off));
        }
        const float mn0 = fmaxf(m0, rm0), mn1 = fmaxf(m1, rm1);
        const float al0 = __expf(m0 - mn0), al1 = __expf(m1 - mn1);

        float rs0 = 0.0f, rs1 = 0.0f;
        unsigned pa[16], pb[16];
#pragma unroll
        for (int nt = 0; nt < 16; nt++) {
            float p0 = __expf(s[nt][0] - mn0);
            float p1 = __expf(s[nt][1] - mn0);
            float p2 = __expf(s[nt][2] - mn1);
            float p3 = __expf(s[nt][3] - mn1);
            rs0 += p0 + p1; rs1 += p2 + p3;
            pa[nt] = h2u(__floats2half2_rn(p0, p1));
            pb[nt] = h2u(__floats2half2_rn(p2, p3));
        }
#pragma unroll
        for (int off = 1; off <= 2; off <<= 1) {
            rs0 += __shfl_xor_sync(0xffffffffu, rs0, off);
            rs1 += __shfl_xor_sync(0xffffffffu, rs1, off);
        }
        l0 = l0 * al0 + rs0;
        l1 = l1 * al1 + rs1;
        m0 = mn0; m1 = mn1;

#pragma unroll
        for (int nt = 0; nt < 16; nt++) {
            O[nt][0] *= al0; O[nt][1] *= al0;
            O[nt][2] *= al1; O[nt][3] *= al1;
        }

        // ---- O += P V : 16q x 128d per warp, P from registers (k = 128 kv) ----
#pragma unroll
        for (int kc = 0; kc < 8; kc++) {
            const int kcol = kc * 16 + hi8;
            unsigned af[4] = { pa[2 * kc], pb[2 * kc], pa[2 * kc + 1], pb[2 * kc + 1] };
#pragma unroll
            for (int p = 0; p < 8; p++) {
                unsigned vq[4];
                ldm4(vq, Vsh + ((p * 16 + ln15) * VTH + kcol) * 2);
#pragma unroll
                for (int sub = 0; sub < 2; sub++) {
                    unsigned bf[2] = { vq[sub], vq[sub + 2] };
                    mma16(O[p * 2 + sub], af, bf);
                }
            }
        }
    }

    const float inv0 = 1.0f / l0, inv1 = 1.0f / l1;
#pragma unroll
    for (int nt = 0; nt < 16; nt++) {
        const int col = h * HD + nt * 8 + 2 * t;
        const size_t r0 = (size_t)(b * SEQL + qt * BQA + wq + g)     * DIM + col;
        const size_t r1 = (size_t)(b * SEQL + qt * BQA + wq + g + 8) * DIM + col;
        *(__half2*)&outp[r0] = __floats2half2_rn(O[nt][0] * inv0, O[nt][1] * inv0);
        *(__half2*)&outp[r1] = __floats2half2_rn(O[nt][2] * inv1, O[nt][3] * inv1);
    }
}

// ---------------------------------------------------------------------------
extern "C" void kernel_launch(void* const* d_in, const int* in_sizes, int n_in,
                              void* d_out, int out_size)
{
    const float* x  = (const float*)d_in[0];
    const float* pk = (const float*)d_in[1];
    const float* pv = (const float*)d_in[2];
    const float* wq = (const float*)d_in[4];
    const float* wk = (const float*)d_in[5];
    const float* wv = (const float*)d_in[6];
    const float* wo = (const float*)d_in[7];

    float* out  = (float*)d_out;
    float* kall = out  + (size_t)BATCH * SEQL * DIM;
    float* vall = kall + (size_t)BATCH * TTOT * DIM;

    float *qbuf; __half *ah, *xh, *wh, *kh, *vt;
    cudaGetSymbolAddress((void**)&qbuf, g_q);
    cudaGetSymbolAddress((void**)&ah,   g_ah);
    cudaGetSymbolAddress((void**)&xh,   g_xh);
    cudaGetSymbolAddress((void**)&wh,   g_wh);
    cudaGetSymbolAddress((void**)&kh,   g_kh);
    cudaGetSymbolAddress((void**)&vt,   g_vt);

    {
        const int tot = 2 * BATCH * HISTL * DIM / 4;
        concat_half_kernel<<<(tot + 255) / 256, 256>>>(pk, pv, kall, vall, kh);
    }
    {
        const int nx4 = MROWS * DIM / 4;
        cvt_f16_kernel<<<(nx4 + 255) / 256, 256>>>(x, xh, nx4);
        const int nwtot = 4 * DIM * DIM / 4;
        cvt_w4_kernel<<<(nwtot + 255) / 256, 256>>>(wq, wk, wv, wo, wh);
    }

    const int gsm3 = (int)(GST * STG3 * sizeof(__half));  // 46080
    cudaFuncSetAttribute(gemm_f16_qkv, cudaFuncAttributeMaxDynamicSharedMemorySize, gsm3);
    cudaFuncSetAttribute(gemm_f16_o,   cudaFuncAttributeMaxDynamicSharedMemorySize, gsm3);

    gemm_f16_qkv<<<dim3(DIM / 128, MROWS / 64, 3), 256, gsm3>>>(
        xh, wh, qbuf, kall, vall, kh);

    vtrans_kernel<<<dim3(TTOT / 64, HD / 64, BATCH * NHEAD), 256>>>(vall, vt);

    cudaFuncSetAttribute(attn_f16, cudaFuncAttributeMaxDynamicSharedMemorySize, ATT_SMEM);
    attn_f16<<<dim3(SEQL / BQA, NHEAD, BATCH), 256, ATT_SMEM>>>(qbuf, kh, vt, ah);

    gemm_f16_o<<<dim3(DIM / 128, MROWS / 64), 256, gsm3>>>(
        ah, wh + 3 * (size_t)DIM * DIM, out);
}